// round 4
// baseline (speedup 1.0000x reference)
#include <cuda_runtime.h>
#include <math_constants.h>
#include <cstdint>

#define BATCH 32
#define SEQ   2048
#define CDIM  384
#define HDIM  64
#define M_TOT (BATCH*SEQ)

// scratch (tf32-rounded):
//   g_k, g_q : [B*T][p(h)]   (column-permuted; q pre-scaled by 0.125)
//   g_vt     : [tile64][h][p(s)]  (per-64-row-tile transposed + s-permuted)
//   g_wt     : [3][col][p(kc)]    (weights transposed + kc-permuted)
__device__ __align__(16) float g_k [M_TOT*HDIM];
__device__ __align__(16) float g_q [M_TOT*HDIM];
__device__ __align__(16) float g_vt[M_TOT*HDIM];
__device__ __align__(16) float g_wt[3][CDIM*HDIM];

__device__ __forceinline__ int perm8(int h) {
    return (h & ~7) | ((h & 3) << 1) | ((h >> 2) & 1);
}
__device__ __forceinline__ float f2tf(float f) {
    uint32_t r;
    asm("cvt.rna.tf32.f32 %0, %1;" : "=r"(r) : "f"(f));
    return __uint_as_float(r);
}
__device__ __forceinline__ uint32_t f2u(float f) { return __float_as_uint(f); }

// D += A@B, m16n8k8 tf32, A row-major, B col-major
__device__ __forceinline__ void mma8(float* d, const uint32_t* a, uint32_t b0, uint32_t b1) {
    asm volatile("mma.sync.aligned.m16n8k8.row.col.f32.tf32.tf32.f32 "
        "{%0,%1,%2,%3}, {%4,%5,%6,%7}, {%8,%9}, {%0,%1,%2,%3};"
        : "+f"(d[0]), "+f"(d[1]), "+f"(d[2]), "+f"(d[3])
        : "r"(a[0]), "r"(a[1]), "r"(a[2]), "r"(a[3]), "r"(b0), "r"(b1));
}

// ---------------------------------------------------------------------------
// Prep: W [kc][col] -> g_wt [ww][col*384 + perm8(kc)], tf32-rounded. One-shot.
// ---------------------------------------------------------------------------
__global__ void prep_w(const float* __restrict__ Wk, const float* __restrict__ Wq,
                       const float* __restrict__ Wv)
{
    int e = blockIdx.x * 256 + threadIdx.x;          // 0 .. 3*24576-1
    int ww = e / (CDIM * HDIM);
    int r  = e % (CDIM * HDIM);
    int kc = r >> 6, col = r & 63;
    const float* W = (ww == 0) ? Wk : (ww == 1) ? Wq : Wv;
    g_wt[ww][col * CDIM + perm8(kc)] = f2tf(W[kc * HDIM + col]);
}

// ---------------------------------------------------------------------------
// Projection: M-tile 128, 256 threads / 8 warps. Warp (w&3)=row quarter (2 mt),
// (w>>2)=col half (4 n8 per weight). tf32 mma, perm-LDS.64 fragments.
// Outputs written permuted/transposed per header comment.
// ---------------------------------------------------------------------------
#define PROJ_SMEM ((128*40 + 3*64*40) * (int)sizeof(float))

__global__ __launch_bounds__(256, 1) void proj_kernel(const float* __restrict__ x)
{
    extern __shared__ __align__(16) float psm[];
    float* xs  = psm;                 // [r][p(c)] stride 40
    float* wst = psm + 128 * 40;      // [ww][col][p(kc)] stride 40

    const int tid  = threadIdx.x;
    const int lane = tid & 31;
    const int w    = tid >> 5;
    const int rq   = (w & 3) * 32;          // warp row offset in tile
    const int nb   = (w >> 2) * 32;         // warp col offset
    const int row0 = blockIdx.x * 128;

    float acc[3][2][4][4];                  // [weight][mt][ntl][frag]
#pragma unroll
    for (int a = 0; a < 3; a++)
#pragma unroll
        for (int b = 0; b < 2; b++)
#pragma unroll
            for (int c = 0; c < 4; c++)
#pragma unroll
                for (int d = 0; d < 4; d++) acc[a][b][c][d] = 0.f;

    for (int c0 = 0; c0 < CDIM; c0 += 32) {
        __syncthreads();
        // x tile 128x32 -> tf32 -> perm-scatter
#pragma unroll
        for (int t = 0; t < 4; t++) {
            int fidx = tid + t * 256;                // 0..1023
            int r = fidx >> 3, c4 = (fidx & 7) * 4;
            float4 v = *(const float4*)&x[(size_t)(row0 + r) * CDIM + c0 + c4];
            xs[r * 40 + perm8(c4 + 0)] = f2tf(v.x);
            xs[r * 40 + perm8(c4 + 1)] = f2tf(v.y);
            xs[r * 40 + perm8(c4 + 2)] = f2tf(v.z);
            xs[r * 40 + perm8(c4 + 3)] = f2tf(v.w);
        }
        // W tiles: straight f4 copy of pre-permuted g_wt (64 cols x 32 kc each)
#pragma unroll
        for (int ww = 0; ww < 3; ww++)
#pragma unroll
            for (int t = 0; t < 2; t++) {
                int fidx = tid + t * 256;            // 0..511
                int col = fidx >> 3, kc4 = (fidx & 7) * 4;
                *(float4*)&wst[ww * 64 * 40 + col * 40 + kc4] =
                    *(const float4*)&g_wt[ww][col * CDIM + c0 + kc4];
            }
        __syncthreads();

#pragma unroll
        for (int kt = 0; kt < 4; kt++) {
            int kb = kt * 8 + 2 * (lane & 3);
            uint32_t a[2][4];
#pragma unroll
            for (int mt = 0; mt < 2; mt++) {
                float2 lo = *(const float2*)&xs[(rq + mt * 16 + (lane >> 2)) * 40 + kb];
                float2 hi = *(const float2*)&xs[(rq + mt * 16 + (lane >> 2) + 8) * 40 + kb];
                a[mt][0] = f2u(lo.x); a[mt][1] = f2u(hi.x);
                a[mt][2] = f2u(lo.y); a[mt][3] = f2u(hi.y);
            }
#pragma unroll
            for (int ww = 0; ww < 3; ww++)
#pragma unroll
                for (int ntl = 0; ntl < 4; ntl++) {
                    int n0 = nb + ntl * 8 + (lane >> 2);
                    float2 b = *(const float2*)&wst[ww * 64 * 40 + n0 * 40 + kb];
#pragma unroll
                    for (int mt = 0; mt < 2; mt++)
                        mma8(acc[ww][mt][ntl], a[mt], f2u(b.x), f2u(b.y));
                }
        }
    }

    // epilogue: k/q col-permuted, v tile-transposed+permuted, all tf32-rounded
#pragma unroll
    for (int mt = 0; mt < 2; mt++)
#pragma unroll
        for (int ntl = 0; ntl < 4; ntl++) {
            int sl = rq + mt * 16 + (lane >> 2);     // local row 0..127
            int rg = row0 + sl;
            int cg = nb + ntl * 8 + 2 * (lane & 3);
            int pc0 = perm8(cg), pc1 = perm8(cg + 1);
            const float* ak = acc[0][mt][ntl];
            const float* aq = acc[1][mt][ntl];
            const float* av = acc[2][mt][ntl];
            size_t r0 = (size_t)rg * HDIM, r1 = (size_t)(rg + 8) * HDIM;
            g_k[r0 + pc0] = f2tf(ak[0]); g_k[r0 + pc1] = f2tf(ak[1]);
            g_k[r1 + pc0] = f2tf(ak[2]); g_k[r1 + pc1] = f2tf(ak[3]);
            g_q[r0 + pc0] = f2tf(aq[0] * 0.125f); g_q[r0 + pc1] = f2tf(aq[1] * 0.125f);
            g_q[r1 + pc0] = f2tf(aq[2] * 0.125f); g_q[r1 + pc1] = f2tf(aq[3] * 0.125f);
            int tile0 = blockIdx.x * 2 + (sl >> 6);
            int ps0 = perm8(sl & 63), ps1 = perm8((sl + 8) & 63);
            size_t v0 = ((size_t)tile0 * 64 + cg) * 64;
            size_t v1 = ((size_t)tile0 * 64 + cg + 1) * 64;
            g_vt[v0 + ps0] = f2tf(av[0]); g_vt[v1 + ps0] = f2tf(av[1]);
            g_vt[v0 + ps1] = f2tf(av[2]); g_vt[v1 + ps1] = f2tf(av[3]);
        }
}

// ---------------------------------------------------------------------------
// Flash attention (causal), tf32 mma, perm-LDS.64 fragments.
// Q-tile 64, K-tile 64, 4 warps; warp w owns rows 16w..16w+15.
// smem 72KB: qs/ks [r|s][p(h)] str 72, vst [h][p(s)] str 72, ps [r][p(c)] str 72.
// ---------------------------------------------------------------------------
#define ATT_SMEM (4 * 64 * 72 * (int)sizeof(float))

__global__ __launch_bounds__(128, 3) void attn_kernel(float* __restrict__ out)
{
    extern __shared__ __align__(16) float sm[];
    float* qs  = sm;
    float* ks  = sm + 64 * 72;
    float* vst = sm + 2 * 64 * 72;
    float* ps  = sm + 3 * 64 * 72;

    const int tid  = threadIdx.x;
    const int lane = tid & 31;
    const int w    = tid >> 5;
    const int qt   = (gridDim.x - 1) - blockIdx.x;   // heavy tiles first
    const int b    = blockIdx.y;
    const int qrow0 = qt * 64;
    const size_t base = (size_t)b * SEQ * HDIM;

    // q fill: straight f4 copy (g_q already col-permuted)
#pragma unroll
    for (int t = 0; t < 8; t++) {
        int fidx = tid + t * 128;
        int r = fidx >> 4, c4 = (fidx & 15) * 4;
        *(float4*)&qs[r * 72 + c4] =
            *(const float4*)&g_q[base + (size_t)(qrow0 + r) * HDIM + c4];
    }

    float o[8][4];
#pragma unroll
    for (int nt = 0; nt < 8; nt++)
#pragma unroll
        for (int e = 0; e < 4; e++) o[nt][e] = 0.f;
    float m0 = -CUDART_INF_F, m1 = -CUDART_INF_F, l0 = 0.f, l1 = 0.f;

    const int rlo = 16 * w + (lane >> 2);
    const int rhi = rlo + 8;
    const int pc0 = perm8(2 * (lane & 3));
    const int pc1 = perm8(2 * (lane & 3) + 1);

    for (int kt = 0; kt <= qt; kt++) {
        __syncthreads();   // prior GEMMs drained before overwrite
        // ks: straight f4 copy; vst: straight f4 copy of pre-transposed g_vt
        const size_t vtb = ((size_t)(b * 32 + kt) * 64) * 64;
#pragma unroll
        for (int t = 0; t < 8; t++) {
            int fidx = tid + t * 128;
            int r = fidx >> 4, c4 = (fidx & 15) * 4;
            *(float4*)&ks[r * 72 + c4] =
                *(const float4*)&g_k[base + (size_t)(kt * 64 + r) * HDIM + c4];
            *(float4*)&vst[r * 72 + c4] = *(const float4*)&g_vt[vtb + r * 64 + c4];
        }
        __syncthreads();

        // GEMM1: S = q @ k^T
        float s[8][4];
#pragma unroll
        for (int nt = 0; nt < 8; nt++)
#pragma unroll
            for (int e = 0; e < 4; e++) s[nt][e] = 0.f;

#pragma unroll
        for (int kt8 = 0; kt8 < 8; kt8++) {
            int kb = kt8 * 8 + 2 * (lane & 3);
            float2 alo = *(const float2*)&qs[rlo * 72 + kb];
            float2 ahi = *(const float2*)&qs[rhi * 72 + kb];
            uint32_t a[4] = {f2u(alo.x), f2u(ahi.x), f2u(alo.y), f2u(ahi.y)};
#pragma unroll
            for (int nt = 0; nt < 8; nt++) {
                int sr = nt * 8 + (lane >> 2);
                float2 bb = *(const float2*)&ks[sr * 72 + kb];
                mma8(s[nt], a, f2u(bb.x), f2u(bb.y));
            }
        }

        // causal mask on diagonal tile
        if (kt == qt) {
            int rg = 16 * w + (lane >> 2);
            int c0 = 2 * (lane & 3);
#pragma unroll
            for (int nt = 0; nt < 8; nt++) {
                int cg = c0 + 8 * nt;
                if (cg     > rg)     s[nt][0] = -CUDART_INF_F;
                if (cg + 1 > rg)     s[nt][1] = -CUDART_INF_F;
                if (cg     > rg + 8) s[nt][2] = -CUDART_INF_F;
                if (cg + 1 > rg + 8) s[nt][3] = -CUDART_INF_F;
            }
        }

        // online softmax (two rows/thread; quad reductions)
        float mx0 = -CUDART_INF_F, mx1 = -CUDART_INF_F;
#pragma unroll
        for (int nt = 0; nt < 8; nt++) {
            mx0 = fmaxf(mx0, fmaxf(s[nt][0], s[nt][1]));
            mx1 = fmaxf(mx1, fmaxf(s[nt][2], s[nt][3]));
        }
        mx0 = fmaxf(mx0, __shfl_xor_sync(0xffffffffu, mx0, 1, 4));
        mx0 = fmaxf(mx0, __shfl_xor_sync(0xffffffffu, mx0, 2, 4));
        mx1 = fmaxf(mx1, __shfl_xor_sync(0xffffffffu, mx1, 1, 4));
        mx1 = fmaxf(mx1, __shfl_xor_sync(0xffffffffu, mx1, 2, 4));

        float nm0 = fmaxf(m0, mx0), nm1 = fmaxf(m1, mx1);
        float al0 = __expf(m0 - nm0), al1 = __expf(m1 - nm1);
        m0 = nm0; m1 = nm1;

        float sum0 = 0.f, sum1 = 0.f;
#pragma unroll
        for (int nt = 0; nt < 8; nt++) {
            s[nt][0] = __expf(s[nt][0] - nm0); sum0 += s[nt][0];
            s[nt][1] = __expf(s[nt][1] - nm0); sum0 += s[nt][1];
            s[nt][2] = __expf(s[nt][2] - nm1); sum1 += s[nt][2];
            s[nt][3] = __expf(s[nt][3] - nm1); sum1 += s[nt][3];
        }
        sum0 += __shfl_xor_sync(0xffffffffu, sum0, 1, 4);
        sum0 += __shfl_xor_sync(0xffffffffu, sum0, 2, 4);
        sum1 += __shfl_xor_sync(0xffffffffu, sum1, 1, 4);
        sum1 += __shfl_xor_sync(0xffffffffu, sum1, 2, 4);
        l0 = l0 * al0 + sum0;
        l1 = l1 * al1 + sum1;
#pragma unroll
        for (int nt = 0; nt < 8; nt++) {
            o[nt][0] *= al0; o[nt][1] *= al0;
            o[nt][2] *= al1; o[nt][3] *= al1;
        }

        // store P (tf32) perm-scattered into warp-private ps rows
#pragma unroll
        for (int nt = 0; nt < 8; nt++) {
            int cb = nt * 8;
            ps[rlo * 72 + cb + pc0] = f2tf(s[nt][0]);
            ps[rlo * 72 + cb + pc1] = f2tf(s[nt][1]);
            ps[rhi * 72 + cb + pc0] = f2tf(s[nt][2]);
            ps[rhi * 72 + cb + pc1] = f2tf(s[nt][3]);
        }
        __syncwarp();

        // GEMM2: O += P @ V
#pragma unroll
        for (int st8 = 0; st8 < 8; st8++) {
            int cb = st8 * 8 + 2 * (lane & 3);
            float2 plo = *(const float2*)&ps[rlo * 72 + cb];
            float2 phi = *(const float2*)&ps[rhi * 72 + cb];
            uint32_t pa[4] = {f2u(plo.x), f2u(phi.x), f2u(plo.y), f2u(phi.y)};
#pragma unroll
            for (int nt = 0; nt < 8; nt++) {
                int hc = nt * 8 + (lane >> 2);
                float2 bb = *(const float2*)&vst[hc * 72 + cb];
                mma8(o[nt], pa, f2u(bb.x), f2u(bb.y));
            }
        }
    }

    // epilogue (canonical h columns)
    float i0 = 1.f / l0, i1 = 1.f / l1;
    int rg = qrow0 + 16 * w + (lane >> 2);
#pragma unroll
    for (int nt = 0; nt < 8; nt++) {
        int cg = nt * 8 + 2 * (lane & 3);
        *(float2*)&out[base + (size_t)rg * HDIM + cg] =
            make_float2(o[nt][0] * i0, o[nt][1] * i0);
        *(float2*)&out[base + (size_t)(rg + 8) * HDIM + cg] =
            make_float2(o[nt][2] * i1, o[nt][3] * i1);
    }
}

// ---------------------------------------------------------------------------
extern "C" void kernel_launch(void* const* d_in, const int* in_sizes, int n_in,
                              void* d_out, int out_size)
{
    const float* x  = (const float*)d_in[0];
    const float* Wk = (const float*)d_in[1];
    const float* Wq = (const float*)d_in[2];
    const float* Wv = (const float*)d_in[3];
    float* out = (float*)d_out;

    prep_w<<<(3 * CDIM * HDIM) / 256, 256>>>(Wk, Wq, Wv);

    cudaFuncSetAttribute(proj_kernel, cudaFuncAttributeMaxDynamicSharedMemorySize,
                         PROJ_SMEM);
    proj_kernel<<<M_TOT / 128, 256, PROJ_SMEM>>>(x);

    cudaFuncSetAttribute(attn_kernel, cudaFuncAttributeMaxDynamicSharedMemorySize,
                         ATT_SMEM);
    dim3 grid(SEQ / 64, BATCH);
    attn_kernel<<<grid, 128, ATT_SMEM>>>(out);
}